// round 2
// baseline (speedup 1.0000x reference)
#include <cuda_runtime.h>
#include <math.h>

#define B_ 2
#define W_ 2048
#define C_ 1024
#define N_ 16
#define K_ 64
#define HEADS (B_*N_)

__device__ float g_P [B_*N_*W_*K_];   // P in [b][n][w][k] layout
__device__ float g_M [HEADS*K_*K_];   // mm per head
__device__ float g_Ng[B_*W_*C_];      // nudged in [b][w][c] layout

// ---------------------------------------------------------------------------
// GEMM: out[r][c] = sum_k A[r][k] * Wt[c][k] + bias[c]
// 128x128 tile, 256 threads, 8x8 micro, kt=16, transposed smem, reg prefetch.
// MODE 0 (proj): A = param, write g_P head layout. MODE 1 (mix): A=g_Ng, out.
// ---------------------------------------------------------------------------
template<int MODE>
__global__ __launch_bounds__(256)
void gemm_kernel(const float* __restrict__ A_, const float* __restrict__ Wt,
                 const float* __restrict__ bias, float* __restrict__ out) {
    __shared__ __align__(16) float As[16*132];
    __shared__ __align__(16) float Bs[16*132];
    const int tx = threadIdx.x, ty = threadIdx.y;
    const int t  = ty*16 + tx;
    const int r0 = blockIdx.y*128, c0 = blockIdx.x*128;
    const float* Ain = (MODE == 0) ? A_ : g_Ng;

    const int lrow = t >> 2;        // 0..63
    const int lk   = (t & 3) * 4;   // 0,4,8,12
    const float* ap0 = Ain + (size_t)(r0 + lrow)*C_ + lk;
    const float* ap1 = ap0 + (size_t)64*C_;
    const float* bp0 = Wt  + (size_t)(c0 + lrow)*C_ + lk;
    const float* bp1 = bp0 + (size_t)64*C_;

    float4 pa0 = *(const float4*)ap0;
    float4 pa1 = *(const float4*)ap1;
    float4 pb0 = *(const float4*)bp0;
    float4 pb1 = *(const float4*)bp1;

    float acc[8][8] = {};

    for (int k0 = 0; k0 < C_; k0 += 16) {
        // transposed stores: As[k][m], Bs[k][n]
        As[(lk+0)*132 + lrow] = pa0.x; As[(lk+1)*132 + lrow] = pa0.y;
        As[(lk+2)*132 + lrow] = pa0.z; As[(lk+3)*132 + lrow] = pa0.w;
        As[(lk+0)*132 + 64 + lrow] = pa1.x; As[(lk+1)*132 + 64 + lrow] = pa1.y;
        As[(lk+2)*132 + 64 + lrow] = pa1.z; As[(lk+3)*132 + 64 + lrow] = pa1.w;
        Bs[(lk+0)*132 + lrow] = pb0.x; Bs[(lk+1)*132 + lrow] = pb0.y;
        Bs[(lk+2)*132 + lrow] = pb0.z; Bs[(lk+3)*132 + lrow] = pb0.w;
        Bs[(lk+0)*132 + 64 + lrow] = pb1.x; Bs[(lk+1)*132 + 64 + lrow] = pb1.y;
        Bs[(lk+2)*132 + 64 + lrow] = pb1.z; Bs[(lk+3)*132 + 64 + lrow] = pb1.w;
        __syncthreads();
        if (k0 + 16 < C_) {
            pa0 = *(const float4*)(ap0 + k0 + 16);
            pa1 = *(const float4*)(ap1 + k0 + 16);
            pb0 = *(const float4*)(bp0 + k0 + 16);
            pb1 = *(const float4*)(bp1 + k0 + 16);
        }
        #pragma unroll
        for (int kk = 0; kk < 16; kk++) {
            const float4 a0 = *(const float4*)&As[kk*132 + ty*8];
            const float4 a1 = *(const float4*)&As[kk*132 + ty*8 + 4];
            const float4 b0 = *(const float4*)&Bs[kk*132 + tx*8];
            const float4 b1 = *(const float4*)&Bs[kk*132 + tx*8 + 4];
            const float a[8] = {a0.x,a0.y,a0.z,a0.w,a1.x,a1.y,a1.z,a1.w};
            const float b[8] = {b0.x,b0.y,b0.z,b0.w,b1.x,b1.y,b1.z,b1.w};
            #pragma unroll
            for (int i = 0; i < 8; i++)
                #pragma unroll
                for (int j = 0; j < 8; j++)
                    acc[i][j] = fmaf(a[i], b[j], acc[i][j]);
        }
        __syncthreads();
    }

    #pragma unroll
    for (int i = 0; i < 8; i++) {
        const int r = r0 + ty*8 + i;
        #pragma unroll
        for (int jq = 0; jq < 2; jq++) {
            const int c = c0 + tx*8 + jq*4;
            float4 v;
            v.x = acc[i][jq*4+0] + bias[c+0];
            v.y = acc[i][jq*4+1] + bias[c+1];
            v.z = acc[i][jq*4+2] + bias[c+2];
            v.w = acc[i][jq*4+3] + bias[c+3];
            if (MODE == 0) {
                const int bb = r >> 11, w = r & (W_-1);
                const int n  = c >> 6,  k = c & (K_-1);
                *(float4*)&g_P[(((size_t)(bb*N_+n))*W_ + w)*K_ + k] = v;
            } else {
                *(float4*)&out[(size_t)r*C_ + c] = v;
            }
        }
    }
}

// ---------------------------------------------------------------------------
// Per-head M build: m[k][l] = sum_w P[w][k]*G[w][l]; mask l<=k; mm = m m^T
// ---------------------------------------------------------------------------
__global__ __launch_bounds__(256)
void mbuild_kernel(const float* __restrict__ G) {
    __shared__ __align__(16) float sb[64*65];
    float* Ps = sb;
    float* Gs = sb + 2048;
    const int tx = threadIdx.x, ty = threadIdx.y;
    const int t  = ty*16 + tx;
    const int bn = blockIdx.x;
    const int n  = bn & (N_-1);
    const float* Pp = g_P + (size_t)bn*W_*K_;
    const float* Gp = G   + (size_t)n *W_*K_;

    float m[4][4] = {};
    for (int w0 = 0; w0 < W_; w0 += 32) {
        #pragma unroll
        for (int s = 0; s < 2; s++) {
            const int i4 = t + s*256;
            ((float4*)Ps)[i4] = ((const float4*)(Pp + (size_t)w0*K_))[i4];
            ((float4*)Gs)[i4] = ((const float4*)(Gp + (size_t)w0*K_))[i4];
        }
        __syncthreads();
        #pragma unroll 8
        for (int ww = 0; ww < 32; ww++) {
            float a[4];
            #pragma unroll
            for (int i = 0; i < 4; i++) a[i] = Ps[ww*64 + ty*4 + i];
            const float4 b4 = *(const float4*)&Gs[ww*64 + tx*4];
            const float b[4] = {b4.x, b4.y, b4.z, b4.w};
            #pragma unroll
            for (int i = 0; i < 4; i++)
                #pragma unroll
                for (int j = 0; j < 4; j++)
                    m[i][j] = fmaf(a[i], b[j], m[i][j]);
        }
        __syncthreads();
    }
    #pragma unroll
    for (int i = 0; i < 4; i++)
        #pragma unroll
        for (int j = 0; j < 4; j++)
            if (tx*4 + j > ty*4 + i) m[i][j] = 0.f;
    #pragma unroll
    for (int i = 0; i < 4; i++)
        #pragma unroll
        for (int j = 0; j < 4; j++)
            sb[(ty*4+i)*65 + tx*4 + j] = m[i][j];
    __syncthreads();
    float mm[4][4] = {};
    #pragma unroll 8
    for (int jj = 0; jj < 64; jj++) {
        float a[4], b[4];
        #pragma unroll
        for (int i = 0; i < 4; i++) a[i] = sb[(ty*4+i)*65 + jj];
        #pragma unroll
        for (int j = 0; j < 4; j++) b[j] = sb[(tx*4+j)*65 + jj];
        #pragma unroll
        for (int i = 0; i < 4; i++)
            #pragma unroll
            for (int j = 0; j < 4; j++)
                mm[i][j] = fmaf(a[i], b[j], mm[i][j]);
    }
    #pragma unroll
    for (int i = 0; i < 4; i++)
        #pragma unroll
        for (int j = 0; j < 4; j++)
            g_M[(size_t)bn*K_*K_ + (ty*4+i)*K_ + tx*4 + j] = mm[i][j];
}

// ---------------------------------------------------------------------------
// Flash attention per (head, 64-query tile), vectorized k-chunked inner GEMMs.
// Kt_s pitch 68 so transposed-tile float4 reads are aligned & conflict-light.
// Dynamic smem: Qm_s[64*64] + Ps_s[64*64] + Kt_s[64*68] = 50176 B.
// ---------------------------------------------------------------------------
#define KT_PITCH 68
__global__ __launch_bounds__(256)
void flash_kernel() {
    extern __shared__ __align__(16) float sm[];
    float* Qm_s = sm;            // [64][64]
    float* Ps_s = sm + 4096;     // [64][64]  Pq / exp-scores
    float* Kt_s = sm + 8192;     // [64][68]  M (prologue) / K^T tile

    const int tx = threadIdx.x, ty = threadIdx.y;
    const int t  = ty*16 + tx;
    const int bn = blockIdx.y;
    const int b  = bn >> 4, n = bn & 15;
    const int qt = (int)(gridDim.x - 1) - (int)blockIdx.x;  // heavy first
    const int w0 = qt * 64;
    const float* Pp = g_P + (size_t)bn*W_*K_;
    const float* Mp = g_M + (size_t)bn*K_*K_;

    // Prologue: Pq -> Ps_s (flat), M -> Kt_s (pitch 68)
    #pragma unroll
    for (int s = 0; s < 4; s++) {
        const int i4 = t + s*256;
        ((float4*)Ps_s)[i4] = ((const float4*)(Pp + (size_t)w0*K_))[i4];
        const int row = i4 >> 4, cq = (i4 & 15) * 4;
        *(float4*)&Kt_s[row*KT_PITCH + cq] = ((const float4*)Mp)[i4];
    }
    __syncthreads();
    // Qm = Pq @ M
    {
        float q[4][4] = {};
        #pragma unroll
        for (int c0 = 0; c0 < 64; c0 += 4) {
            float4 a4[4], b4[4];
            #pragma unroll
            for (int i = 0; i < 4; i++) a4[i] = *(const float4*)&Ps_s[(ty*4+i)*64 + c0];
            #pragma unroll
            for (int k = 0; k < 4; k++) b4[k] = *(const float4*)&Kt_s[(c0+k)*KT_PITCH + tx*4];
            float bm[4][4];
            #pragma unroll
            for (int k = 0; k < 4; k++) {
                bm[k][0]=b4[k].x; bm[k][1]=b4[k].y; bm[k][2]=b4[k].z; bm[k][3]=b4[k].w;
            }
            #pragma unroll
            for (int i = 0; i < 4; i++) {
                const float4 a = a4[i];
                #pragma unroll
                for (int j = 0; j < 4; j++)
                    q[i][j] = fmaf(a.x, bm[0][j], fmaf(a.y, bm[1][j],
                               fmaf(a.z, bm[2][j], fmaf(a.w, bm[3][j], q[i][j]))));
            }
        }
        #pragma unroll
        for (int i = 0; i < 4; i++) {
            float4 v = make_float4(q[i][0], q[i][1], q[i][2], q[i][3]);
            *(float4*)&Qm_s[(ty*4+i)*64 + tx*4] = v;
        }
    }

    float mrun[4], lrun[4], O[4][4] = {};
    #pragma unroll
    for (int i = 0; i < 4; i++) { mrun[i] = -INFINITY; lrun[i] = 0.f; }

    for (int v0 = 0; v0 <= w0; v0 += 64) {
        __syncthreads();  // Qm visible (iter 0); Kt_s/Ps_s free (later)
        // K tile transposed: Kt_s[dim][key]
        {
            const int row = t >> 2;          // key 0..63
            const int d0  = (t & 3) * 16;
            const float* src = Pp + (size_t)(v0 + row)*K_ + d0;
            #pragma unroll
            for (int qq = 0; qq < 4; qq++) {
                const float4 v = *(const float4*)(src + qq*4);
                Kt_s[(d0+qq*4+0)*KT_PITCH + row] = v.x;
                Kt_s[(d0+qq*4+1)*KT_PITCH + row] = v.y;
                Kt_s[(d0+qq*4+2)*KT_PITCH + row] = v.z;
                Kt_s[(d0+qq*4+3)*KT_PITCH + row] = v.w;
            }
        }
        __syncthreads();
        // GEMM1: S = Qm @ K^T   (chunked over k by 4)
        float s[4][4] = {};
        #pragma unroll
        for (int c0 = 0; c0 < 64; c0 += 4) {
            float4 a4[4], b4[4];
            #pragma unroll
            for (int i = 0; i < 4; i++) a4[i] = *(const float4*)&Qm_s[(ty*4+i)*64 + c0];
            #pragma unroll
            for (int k = 0; k < 4; k++) b4[k] = *(const float4*)&Kt_s[(c0+k)*KT_PITCH + tx*4];
            float bm[4][4];
            #pragma unroll
            for (int k = 0; k < 4; k++) {
                bm[k][0]=b4[k].x; bm[k][1]=b4[k].y; bm[k][2]=b4[k].z; bm[k][3]=b4[k].w;
            }
            #pragma unroll
            for (int i = 0; i < 4; i++) {
                const float4 a = a4[i];
                #pragma unroll
                for (int j = 0; j < 4; j++)
                    s[i][j] = fmaf(a.x, bm[0][j], fmaf(a.y, bm[1][j],
                               fmaf(a.z, bm[2][j], fmaf(a.w, bm[3][j], s[i][j]))));
            }
        }
        const bool diag = (v0 == w0);
        #pragma unroll
        for (int i = 0; i < 4; i++)
            #pragma unroll
            for (int j = 0; j < 4; j++) {
                s[i][j] *= 0.125f;
                if (diag && (tx*4 + j > ty*4 + i)) s[i][j] = -INFINITY;
            }
        // Online softmax
        #pragma unroll
        for (int i = 0; i < 4; i++) {
            float rmax = fmaxf(fmaxf(s[i][0], s[i][1]), fmaxf(s[i][2], s[i][3]));
            #pragma unroll
            for (int off = 8; off >= 1; off >>= 1)
                rmax = fmaxf(rmax, __shfl_xor_sync(0xffffffffu, rmax, off));
            const float mn    = fmaxf(mrun[i], rmax);
            const float alpha = __expf(mrun[i] - mn);
            float4 pv;
            pv.x = __expf(s[i][0] - mn);
            pv.y = __expf(s[i][1] - mn);
            pv.z = __expf(s[i][2] - mn);
            pv.w = __expf(s[i][3] - mn);
            *(float4*)&Ps_s[(ty*4+i)*64 + tx*4] = pv;
            float rsum = pv.x + pv.y + pv.z + pv.w;
            #pragma unroll
            for (int off = 8; off >= 1; off >>= 1)
                rsum += __shfl_xor_sync(0xffffffffu, rsum, off);
            lrun[i] = lrun[i]*alpha + rsum;
            mrun[i] = mn;
            #pragma unroll
            for (int j = 0; j < 4; j++) O[i][j] *= alpha;
        }
        __syncthreads();
        // GEMM2: O += Ptilde @ V   (V[c][d] = Kt_s[d][c]; chunk over c by 4)
        #pragma unroll
        for (int c0 = 0; c0 < 64; c0 += 4) {
            float4 a4[4], b4[4];
            #pragma unroll
            for (int i = 0; i < 4; i++) a4[i] = *(const float4*)&Ps_s[(ty*4+i)*64 + c0];
            #pragma unroll
            for (int j = 0; j < 4; j++) b4[j] = *(const float4*)&Kt_s[(tx*4+j)*KT_PITCH + c0];
            #pragma unroll
            for (int i = 0; i < 4; i++) {
                const float4 a = a4[i];
                #pragma unroll
                for (int j = 0; j < 4; j++) {
                    const float4 bb = b4[j];
                    O[i][j] = fmaf(a.x, bb.x, fmaf(a.y, bb.y,
                               fmaf(a.z, bb.z, fmaf(a.w, bb.w, O[i][j]))));
                }
            }
        }
    }
    // Epilogue
    #pragma unroll
    for (int i = 0; i < 4; i++) {
        const float inv = 1.0f / lrun[i];
        const int w = w0 + ty*4 + i;
        const float4 o4 = make_float4(O[i][0]*inv, O[i][1]*inv, O[i][2]*inv, O[i][3]*inv);
        *(float4*)&g_Ng[((size_t)(b*W_ + w))*C_ + n*K_ + tx*4] = o4;
    }
}

// ---------------------------------------------------------------------------
extern "C" void kernel_launch(void* const* d_in, const int* in_sizes, int n_in,
                              void* d_out, int out_size) {
    const float* x  = (const float*)d_in[0];
    const float* Wp = (const float*)d_in[1];
    const float* bp = (const float*)d_in[2];
    const float* G  = (const float*)d_in[3];
    const float* Wm = (const float*)d_in[4];
    const float* bm = (const float*)d_in[5];
    float* out = (float*)d_out;

    cudaFuncSetAttribute(flash_kernel, cudaFuncAttributeMaxDynamicSharedMemorySize,
                         (4096 + 4096 + 64*KT_PITCH) * (int)sizeof(float));

    dim3 blk(16, 16);
    gemm_kernel<0><<<dim3(8, 32), blk>>>(x, Wp, bp, nullptr);
    mbuild_kernel<<<32, blk>>>(G);
    flash_kernel<<<dim3(32, 32), blk, (4096 + 4096 + 64*KT_PITCH)*sizeof(float)>>>();
    gemm_kernel<1><<<dim3(8, 32), blk>>>(nullptr, Wm, bm, out);
}

// round 3
// speedup vs baseline: 1.3061x; 1.3061x over previous
#include <cuda_runtime.h>
#include <math.h>

#define B_ 2
#define W_ 2048
#define C_ 1024
#define N_ 16
#define K_ 64
#define HEADS (B_*N_)

__device__ float g_P [B_*N_*W_*K_];   // P in [b][n][w][k] layout
__device__ float g_M [HEADS*K_*K_];   // mm per head
__device__ float g_Ng[B_*W_*C_];      // nudged in [b][w][c] layout

// ---------------------------------------------------------------------------
// GEMM: out[r][c] = sum_k A[r][k] * Wt[c][k] + bias[c]
// 128x128 tile, 256 threads, 8x8 micro in 2x2 groups of 4 (offset +64):
// all smem fragment loads are conflict-free float4 or broadcast.
// ---------------------------------------------------------------------------
template<int MODE>
__global__ __launch_bounds__(256)
void gemm_kernel(const float* __restrict__ A_, const float* __restrict__ Wt,
                 const float* __restrict__ bias, float* __restrict__ out) {
    __shared__ __align__(16) float As[16*132];
    __shared__ __align__(16) float Bs[16*132];
    const int tx = threadIdx.x, ty = threadIdx.y;
    const int t  = ty*16 + tx;
    const int r0 = blockIdx.y*128, c0 = blockIdx.x*128;
    const float* Ain = (MODE == 0) ? A_ : g_Ng;

    const int lrow = t >> 2;
    const int lk   = (t & 3) * 4;
    const float* ap0 = Ain + (size_t)(r0 + lrow)*C_ + lk;
    const float* ap1 = ap0 + (size_t)64*C_;
    const float* bp0 = Wt  + (size_t)(c0 + lrow)*C_ + lk;
    const float* bp1 = bp0 + (size_t)64*C_;

    float4 pa0 = *(const float4*)ap0;
    float4 pa1 = *(const float4*)ap1;
    float4 pb0 = *(const float4*)bp0;
    float4 pb1 = *(const float4*)bp1;

    float acc[8][8] = {};

    for (int k0 = 0; k0 < C_; k0 += 16) {
        As[(lk+0)*132 + lrow] = pa0.x; As[(lk+1)*132 + lrow] = pa0.y;
        As[(lk+2)*132 + lrow] = pa0.z; As[(lk+3)*132 + lrow] = pa0.w;
        As[(lk+0)*132 + 64 + lrow] = pa1.x; As[(lk+1)*132 + 64 + lrow] = pa1.y;
        As[(lk+2)*132 + 64 + lrow] = pa1.z; As[(lk+3)*132 + 64 + lrow] = pa1.w;
        Bs[(lk+0)*132 + lrow] = pb0.x; Bs[(lk+1)*132 + lrow] = pb0.y;
        Bs[(lk+2)*132 + lrow] = pb0.z; Bs[(lk+3)*132 + lrow] = pb0.w;
        Bs[(lk+0)*132 + 64 + lrow] = pb1.x; Bs[(lk+1)*132 + 64 + lrow] = pb1.y;
        Bs[(lk+2)*132 + 64 + lrow] = pb1.z; Bs[(lk+3)*132 + 64 + lrow] = pb1.w;
        __syncthreads();
        if (k0 + 16 < C_) {
            pa0 = *(const float4*)(ap0 + k0 + 16);
            pa1 = *(const float4*)(ap1 + k0 + 16);
            pb0 = *(const float4*)(bp0 + k0 + 16);
            pb1 = *(const float4*)(bp1 + k0 + 16);
        }
        #pragma unroll
        for (int kk = 0; kk < 16; kk++) {
            // row groups: ty*4 and 64+ty*4 ; col groups: tx*4 and 64+tx*4
            const float4 a0 = *(const float4*)&As[kk*132 + ty*4];       // broadcast
            const float4 a1 = *(const float4*)&As[kk*132 + 64 + ty*4];  // broadcast
            const float4 b0 = *(const float4*)&Bs[kk*132 + tx*4];       // conflict-free
            const float4 b1 = *(const float4*)&Bs[kk*132 + 64 + tx*4];  // conflict-free
            const float a[8] = {a0.x,a0.y,a0.z,a0.w,a1.x,a1.y,a1.z,a1.w};
            const float b[8] = {b0.x,b0.y,b0.z,b0.w,b1.x,b1.y,b1.z,b1.w};
            #pragma unroll
            for (int i = 0; i < 8; i++)
                #pragma unroll
                for (int j = 0; j < 8; j++)
                    acc[i][j] = fmaf(a[i], b[j], acc[i][j]);
        }
        __syncthreads();
    }

    #pragma unroll
    for (int i = 0; i < 8; i++) {
        const int r = r0 + (i < 4 ? ty*4 + i : 64 + ty*4 + (i-4));
        #pragma unroll
        for (int jq = 0; jq < 2; jq++) {
            const int c = c0 + (jq == 0 ? tx*4 : 64 + tx*4);
            float4 v;
            v.x = acc[i][jq*4+0] + bias[c+0];
            v.y = acc[i][jq*4+1] + bias[c+1];
            v.z = acc[i][jq*4+2] + bias[c+2];
            v.w = acc[i][jq*4+3] + bias[c+3];
            if (MODE == 0) {
                const int bb = r >> 11, w = r & (W_-1);
                const int n  = c >> 6,  k = c & (K_-1);
                *(float4*)&g_P[(((size_t)(bb*N_+n))*W_ + w)*K_ + k] = v;
            } else {
                *(float4*)&out[(size_t)r*C_ + c] = v;
            }
        }
    }
}

// ---------------------------------------------------------------------------
// Per-head M build (unchanged; tiny cost)
// ---------------------------------------------------------------------------
__global__ __launch_bounds__(256)
void mbuild_kernel(const float* __restrict__ G) {
    __shared__ __align__(16) float sb[64*65];
    float* Ps = sb;
    float* Gs = sb + 2048;
    const int tx = threadIdx.x, ty = threadIdx.y;
    const int t  = ty*16 + tx;
    const int bn = blockIdx.x;
    const int n  = bn & (N_-1);
    const float* Pp = g_P + (size_t)bn*W_*K_;
    const float* Gp = G   + (size_t)n *W_*K_;

    float m[4][4] = {};
    for (int w0 = 0; w0 < W_; w0 += 32) {
        #pragma unroll
        for (int s = 0; s < 2; s++) {
            const int i4 = t + s*256;
            ((float4*)Ps)[i4] = ((const float4*)(Pp + (size_t)w0*K_))[i4];
            ((float4*)Gs)[i4] = ((const float4*)(Gp + (size_t)w0*K_))[i4];
        }
        __syncthreads();
        #pragma unroll 8
        for (int ww = 0; ww < 32; ww++) {
            float a[4];
            #pragma unroll
            for (int i = 0; i < 4; i++) a[i] = Ps[ww*64 + ty*4 + i];
            const float4 b4 = *(const float4*)&Gs[ww*64 + tx*4];
            const float b[4] = {b4.x, b4.y, b4.z, b4.w};
            #pragma unroll
            for (int i = 0; i < 4; i++)
                #pragma unroll
                for (int j = 0; j < 4; j++)
                    m[i][j] = fmaf(a[i], b[j], m[i][j]);
        }
        __syncthreads();
    }
    #pragma unroll
    for (int i = 0; i < 4; i++)
        #pragma unroll
        for (int j = 0; j < 4; j++)
            if (tx*4 + j > ty*4 + i) m[i][j] = 0.f;
    #pragma unroll
    for (int i = 0; i < 4; i++)
        #pragma unroll
        for (int j = 0; j < 4; j++)
            sb[(ty*4+i)*65 + tx*4 + j] = m[i][j];
    __syncthreads();
    float mm[4][4] = {};
    #pragma unroll 8
    for (int jj = 0; jj < 64; jj++) {
        float a[4], b[4];
        #pragma unroll
        for (int i = 0; i < 4; i++) a[i] = sb[(ty*4+i)*65 + jj];
        #pragma unroll
        for (int j = 0; j < 4; j++) b[j] = sb[(tx*4+j)*65 + jj];
        #pragma unroll
        for (int i = 0; i < 4; i++)
            #pragma unroll
            for (int j = 0; j < 4; j++)
                mm[i][j] = fmaf(a[i], b[j], mm[i][j]);
    }
    #pragma unroll
    for (int i = 0; i < 4; i++)
        #pragma unroll
        for (int j = 0; j < 4; j++)
            g_M[(size_t)bn*K_*K_ + (ty*4+i)*K_ + tx*4 + j] = mm[i][j];
}

// ---------------------------------------------------------------------------
// Flash attention: 128-query x 64-key tiles, 8x4 microtile (rows ty*4 & 64+ty*4).
// Scalar-broadcast smem loads; Kt pitch 65 (2-way worst case).
// smem: Qm[128*64] + Ps[128*64] + Kt[64*65] = 82176 B -> 2 CTA/SM.
// ---------------------------------------------------------------------------
#define KTP 65
__global__ __launch_bounds__(256)
void flash_kernel() {
    extern __shared__ __align__(16) float sm[];
    float* Qm_s = sm;             // [128][64]
    float* Ps_s = sm + 8192;      // [128][64]  Pq (prologue) / exp-scores
    float* Kt_s = sm + 16384;     // [64][65]   M (prologue) / K^T tile [dim][key]

    const int tx = threadIdx.x, ty = threadIdx.y;
    const int t  = ty*16 + tx;
    const int bn = blockIdx.y;
    const int b  = bn >> 4, n = bn & 15;
    const int qt = 15 - (int)blockIdx.x;   // heavy tiles first
    const int w0 = qt * 128;
    const float* Pp = g_P + (size_t)bn*W_*K_;
    const float* Mp = g_M + (size_t)bn*K_*K_;

    int R[8];
    #pragma unroll
    for (int i = 0; i < 8; i++) R[i] = (i < 4) ? ty*4 + i : 64 + ty*4 + (i-4);

    // Prologue: Pq[128][64] -> Ps_s, M[64][64] -> Kt_s (pitch 65)
    #pragma unroll
    for (int s = 0; s < 8; s++) {
        const int i4 = t + s*256;
        ((float4*)Ps_s)[i4] = ((const float4*)(Pp + (size_t)w0*K_))[i4];
    }
    #pragma unroll
    for (int s = 0; s < 16; s++) {
        const int idx = t + s*256;
        Kt_s[(idx >> 6)*KTP + (idx & 63)] = Mp[idx];
    }
    __syncthreads();
    // Qm = Pq @ M
    {
        float q[8][4] = {};
        #pragma unroll 8
        for (int kk = 0; kk < 64; kk++) {
            float a[8], bb[4];
            #pragma unroll
            for (int i = 0; i < 8; i++) a[i] = Ps_s[R[i]*64 + kk];
            #pragma unroll
            for (int j = 0; j < 4; j++) bb[j] = Kt_s[kk*KTP + tx*4 + j];
            #pragma unroll
            for (int i = 0; i < 8; i++)
                #pragma unroll
                for (int j = 0; j < 4; j++)
                    q[i][j] = fmaf(a[i], bb[j], q[i][j]);
        }
        #pragma unroll
        for (int i = 0; i < 8; i++)
            *(float4*)&Qm_s[R[i]*64 + tx*4] =
                make_float4(q[i][0], q[i][1], q[i][2], q[i][3]);
    }

    float mrun[8], lrun[8], O[8][4] = {};
    #pragma unroll
    for (int i = 0; i < 8; i++) { mrun[i] = -INFINITY; lrun[i] = 0.f; }

    const int vmax = w0 + 64;   // last key tile covering query w0+127
    for (int v0 = 0; v0 <= vmax; v0 += 64) {
        __syncthreads();  // Qm ready (iter0) / Kt,Ps reusable (later)
        {   // K tile transposed: Kt_s[dim][key]
            const int row = t >> 2;
            const int d0  = (t & 3) * 16;
            const float* src = Pp + (size_t)(v0 + row)*K_ + d0;
            #pragma unroll
            for (int qq = 0; qq < 4; qq++) {
                const float4 v = *(const float4*)(src + qq*4);
                Kt_s[(d0+qq*4+0)*KTP + row] = v.x;
                Kt_s[(d0+qq*4+1)*KTP + row] = v.y;
                Kt_s[(d0+qq*4+2)*KTP + row] = v.z;
                Kt_s[(d0+qq*4+3)*KTP + row] = v.w;
            }
        }
        __syncthreads();
        // GEMM1: S = Qm @ K^T
        float s[8][4] = {};
        #pragma unroll 8
        for (int kk = 0; kk < 64; kk++) {
            float a[8], bb[4];
            #pragma unroll
            for (int i = 0; i < 8; i++) a[i] = Qm_s[R[i]*64 + kk];
            #pragma unroll
            for (int j = 0; j < 4; j++) bb[j] = Kt_s[kk*KTP + tx*4 + j];
            #pragma unroll
            for (int i = 0; i < 8; i++)
                #pragma unroll
                for (int j = 0; j < 4; j++)
                    s[i][j] = fmaf(a[i], bb[j], s[i][j]);
        }
        const bool needmask = (v0 >= w0);
        #pragma unroll
        for (int i = 0; i < 8; i++)
            #pragma unroll
            for (int j = 0; j < 4; j++) {
                s[i][j] *= 0.125f;
                if (needmask && (v0 + tx*4 + j > w0 + R[i])) s[i][j] = -INFINITY;
            }
        // Online softmax (16-lane row groups)
        #pragma unroll
        for (int i = 0; i < 8; i++) {
            float rmax = fmaxf(fmaxf(s[i][0], s[i][1]), fmaxf(s[i][2], s[i][3]));
            #pragma unroll
            for (int off = 8; off >= 1; off >>= 1)
                rmax = fmaxf(rmax, __shfl_xor_sync(0xffffffffu, rmax, off));
            const float mn    = fmaxf(mrun[i], rmax);
            const float alpha = __expf(mrun[i] - mn);
            float4 pv;
            pv.x = __expf(s[i][0] - mn);
            pv.y = __expf(s[i][1] - mn);
            pv.z = __expf(s[i][2] - mn);
            pv.w = __expf(s[i][3] - mn);
            *(float4*)&Ps_s[R[i]*64 + tx*4] = pv;
            float rsum = pv.x + pv.y + pv.z + pv.w;
            #pragma unroll
            for (int off = 8; off >= 1; off >>= 1)
                rsum += __shfl_xor_sync(0xffffffffu, rsum, off);
            lrun[i] = lrun[i]*alpha + rsum;
            mrun[i] = mn;
            #pragma unroll
            for (int j = 0; j < 4; j++) O[i][j] *= alpha;
        }
        __syncthreads();
        // GEMM2: O += Ptilde @ V   (V[key][d] = Kt_s[d][key])
        #pragma unroll 8
        for (int c = 0; c < 64; c++) {
            float a[8], bb[4];
            #pragma unroll
            for (int i = 0; i < 8; i++) a[i] = Ps_s[R[i]*64 + c];
            #pragma unroll
            for (int j = 0; j < 4; j++) bb[j] = Kt_s[(tx*4+j)*KTP + c];
            #pragma unroll
            for (int i = 0; i < 8; i++)
                #pragma unroll
                for (int j = 0; j < 4; j++)
                    O[i][j] = fmaf(a[i], bb[j], O[i][j]);
        }
    }
    // Epilogue
    #pragma unroll
    for (int i = 0; i < 8; i++) {
        const float inv = 1.0f / lrun[i];
        const int w = w0 + R[i];
        *(float4*)&g_Ng[((size_t)(b*W_ + w))*C_ + n*K_ + tx*4] =
            make_float4(O[i][0]*inv, O[i][1]*inv, O[i][2]*inv, O[i][3]*inv);
    }
}

// ---------------------------------------------------------------------------
extern "C" void kernel_launch(void* const* d_in, const int* in_sizes, int n_in,
                              void* d_out, int out_size) {
    const float* x  = (const float*)d_in[0];
    const float* Wp = (const float*)d_in[1];
    const float* bp = (const float*)d_in[2];
    const float* G  = (const float*)d_in[3];
    const float* Wm = (const float*)d_in[4];
    const float* bm = (const float*)d_in[5];
    float* out = (float*)d_out;

    cudaFuncSetAttribute(flash_kernel, cudaFuncAttributeMaxDynamicSharedMemorySize,
                         (8192 + 8192 + 64*KTP) * (int)sizeof(float));

    dim3 blk(16, 16);
    gemm_kernel<0><<<dim3(8, 32), blk>>>(x, Wp, bp, nullptr);
    mbuild_kernel<<<32, blk>>>(G);
    flash_kernel<<<dim3(16, 32), blk, (8192 + 8192 + 64*KTP)*sizeof(float)>>>();
    gemm_kernel<1><<<dim3(8, 32), blk>>>(nullptr, Wm, bm, out);
}

// round 5
// speedup vs baseline: 1.5864x; 1.2146x over previous
#include <cuda_runtime.h>
#include <cuda_bf16.h>
#include <math.h>
#include <cstdint>

#define B_ 2
#define W_ 2048
#define C_ 1024
#define N_ 16
#define K_ 64
#define HEADS (B_*N_)

__device__ float g_P [B_*N_*W_*K_];   // P in [b][n][w][k] layout
__device__ float g_M [HEADS*K_*K_];   // mm per head
__device__ float g_Ng[B_*W_*C_];      // nudged in [b][w][c] layout

// bf16 split buffers (reused: x then Ng for A; Wp then Wm for B)
__device__ __nv_bfloat16 g_Ahi[(size_t)B_*W_*C_];
__device__ __nv_bfloat16 g_Alo[(size_t)B_*W_*C_];
__device__ __nv_bfloat16 g_Bhi[(size_t)C_*C_];
__device__ __nv_bfloat16 g_Blo[(size_t)C_*C_];

// ---------------- helpers (plain sm_80-class PTX only) ----------------
__device__ __forceinline__ uint32_t smem_u32(const void* p) {
    uint32_t a;
    asm("{ .reg .u64 t; cvta.to.shared.u64 t, %1; cvt.u32.u64 %0, t; }" : "=r"(a) : "l"(p));
    return a;
}
__device__ __forceinline__ void ldsm_x4(uint32_t* r, uint32_t addr) {
    asm volatile("ldmatrix.sync.aligned.m8n8.x4.shared.b16 {%0,%1,%2,%3}, [%4];"
        : "=r"(r[0]), "=r"(r[1]), "=r"(r[2]), "=r"(r[3]) : "r"(addr));
}
__device__ __forceinline__ void ldsm_x2(uint32_t* r, uint32_t addr) {
    asm volatile("ldmatrix.sync.aligned.m8n8.x2.shared.b16 {%0,%1}, [%2];"
        : "=r"(r[0]), "=r"(r[1]) : "r"(addr));
}
__device__ __forceinline__ void mma_bf16(float* d, const uint32_t* a, const uint32_t* b) {
    asm volatile("mma.sync.aligned.m16n8k16.row.col.f32.bf16.bf16.f32 "
        "{%0,%1,%2,%3}, {%4,%5,%6,%7}, {%8,%9}, {%0,%1,%2,%3};"
        : "+f"(d[0]), "+f"(d[1]), "+f"(d[2]), "+f"(d[3])
        : "r"(a[0]), "r"(a[1]), "r"(a[2]), "r"(a[3]), "r"(b[0]), "r"(b[1]));
}

// ---------------------------------------------------------------------------
// fp32 -> (bf16 hi, bf16 lo) split conversion
// ---------------------------------------------------------------------------
__global__ __launch_bounds__(256)
void convert_kernel(const float* __restrict__ src, __nv_bfloat16* __restrict__ hi,
                    __nv_bfloat16* __restrict__ lo, int n4) {
    const int i = blockIdx.x * blockDim.x + threadIdx.x;
    if (i >= n4) return;
    const float4 v = ((const float4*)src)[i];
    __nv_bfloat16 h0 = __float2bfloat16(v.x), h1 = __float2bfloat16(v.y);
    __nv_bfloat16 h2 = __float2bfloat16(v.z), h3 = __float2bfloat16(v.w);
    __nv_bfloat16 l0 = __float2bfloat16(v.x - __bfloat162float(h0));
    __nv_bfloat16 l1 = __float2bfloat16(v.y - __bfloat162float(h1));
    __nv_bfloat16 l2 = __float2bfloat16(v.z - __bfloat162float(h2));
    __nv_bfloat16 l3 = __float2bfloat16(v.w - __bfloat162float(h3));
    ((__nv_bfloat162*)hi)[i*2+0] = __halves2bfloat162(h0, h1);
    ((__nv_bfloat162*)hi)[i*2+1] = __halves2bfloat162(h2, h3);
    ((__nv_bfloat162*)lo)[i*2+0] = __halves2bfloat162(l0, l1);
    ((__nv_bfloat162*)lo)[i*2+1] = __halves2bfloat162(l2, l3);
}

// ---------------------------------------------------------------------------
// HMMA bf16x3 GEMM: out[r][c] = sum_k A[r][k]*Wt[c][k] + bias[c]
// 128x128 CTA tile, 8 warps (2x4), warp tile 64x32 (4x4 m16n8k16), K chunk 64.
// smem pitch 72 bf16 (rows 16B aligned). MODE 0 -> g_P head layout; 1 -> out.
// ---------------------------------------------------------------------------
#define PITCH 72
#define MG_SMEM (4 * 128 * PITCH * 2)   // 73728 B

template<int MODE>
__global__ __launch_bounds__(256)
void mma_gemm(const float* __restrict__ bias, float* __restrict__ out) {
    extern __shared__ __align__(16) __nv_bfloat16 sb[];
    __nv_bfloat16* Ash = sb;
    __nv_bfloat16* Asl = sb + 128*PITCH;
    __nv_bfloat16* Bsh = sb + 2*128*PITCH;
    __nv_bfloat16* Bsl = sb + 3*128*PITCH;
    const int tid = threadIdx.x, lane = tid & 31, wid = tid >> 5;
    const int wm = wid >> 2, wn = wid & 3;          // 2 x 4 warp grid
    const int r0 = blockIdx.y*128, c0 = blockIdx.x*128;

    float acc[4][4][4] = {};   // [mi][ni][frag]

    for (int k0 = 0; k0 < C_; k0 += 64) {
        #pragma unroll
        for (int s = 0; s < 4; s++) {
            const int idx = tid + s*256;            // 0..1023
            const int row = idx >> 3, q = idx & 7;  // 128 rows x 8 uint4
            const size_t ga = (size_t)(r0 + row)*C_ + k0 + q*8;
            const size_t gb = (size_t)(c0 + row)*C_ + k0 + q*8;
            *(uint4*)&Ash[row*PITCH + q*8] = *(const uint4*)(g_Ahi + ga);
            *(uint4*)&Asl[row*PITCH + q*8] = *(const uint4*)(g_Alo + ga);
            *(uint4*)&Bsh[row*PITCH + q*8] = *(const uint4*)(g_Bhi + gb);
            *(uint4*)&Bsl[row*PITCH + q*8] = *(const uint4*)(g_Blo + gb);
        }
        __syncthreads();
        #pragma unroll
        for (int ks = 0; ks < 4; ks++) {
            const int kk = ks * 16;
            // B fragments first (8 regs hi + 8 lo)
            uint32_t bh[4][2], bl[4][2];
            {
                const int row = wn*32 + (lane & 7);
                const int col = kk + ((lane >> 3) & 1) * 8;
                #pragma unroll
                for (int ni = 0; ni < 4; ni++) {
                    ldsm_x2(bh[ni], smem_u32(&Bsh[(row + ni*8)*PITCH + col]));
                    ldsm_x2(bl[ni], smem_u32(&Bsl[(row + ni*8)*PITCH + col]));
                }
            }
            #pragma unroll
            for (int mi = 0; mi < 4; mi++) {
                uint32_t ah[4], al[4];
                const int row = wm*64 + mi*16 + (lane & 15);
                const int col = kk + (lane >> 4) * 8;
                ldsm_x4(ah, smem_u32(&Ash[row*PITCH + col]));
                ldsm_x4(al, smem_u32(&Asl[row*PITCH + col]));
                #pragma unroll
                for (int ni = 0; ni < 4; ni++) {
                    mma_bf16(acc[mi][ni], ah, bh[ni]);
                    mma_bf16(acc[mi][ni], ah, bl[ni]);
                    mma_bf16(acc[mi][ni], al, bh[ni]);
                }
            }
        }
        __syncthreads();
    }

    // Epilogue: d frag -> row = lane/4 (+8), col pair = (lane%4)*2
    #pragma unroll
    for (int mi = 0; mi < 4; mi++) {
        #pragma unroll
        for (int ni = 0; ni < 4; ni++) {
            #pragma unroll
            for (int h = 0; h < 2; h++) {
                const int r = r0 + wm*64 + mi*16 + (lane >> 2) + h*8;
                const int c = c0 + wn*32 + ni*8 + (lane & 3)*2;
                float2 v;
                v.x = acc[mi][ni][h*2+0] + __ldg(bias + c);
                v.y = acc[mi][ni][h*2+1] + __ldg(bias + c + 1);
                if (MODE == 0) {
                    const int bb = r >> 11, w = r & (W_-1);
                    const int n  = c >> 6,  kb = c & (K_-1);
                    *(float2*)&g_P[(((size_t)(bb*N_+n))*W_ + w)*K_ + kb] = v;
                } else {
                    *(float2*)&out[(size_t)r*C_ + c] = v;
                }
            }
        }
    }
}

// ---------------------------------------------------------------------------
// Per-head M build (unchanged)
// ---------------------------------------------------------------------------
__global__ __launch_bounds__(256)
void mbuild_kernel(const float* __restrict__ G) {
    __shared__ __align__(16) float sb[64*65];
    float* Ps = sb;
    float* Gs = sb + 2048;
    const int tx = threadIdx.x, ty = threadIdx.y;
    const int t  = ty*16 + tx;
    const int bn = blockIdx.x;
    const int n  = bn & (N_-1);
    const float* Pp = g_P + (size_t)bn*W_*K_;
    const float* Gp = G   + (size_t)n *W_*K_;

    float m[4][4] = {};
    for (int w0 = 0; w0 < W_; w0 += 32) {
        #pragma unroll
        for (int s = 0; s < 2; s++) {
            const int i4 = t + s*256;
            ((float4*)Ps)[i4] = ((const float4*)(Pp + (size_t)w0*K_))[i4];
            ((float4*)Gs)[i4] = ((const float4*)(Gp + (size_t)w0*K_))[i4];
        }
        __syncthreads();
        #pragma unroll 8
        for (int ww = 0; ww < 32; ww++) {
            float a[4];
            #pragma unroll
            for (int i = 0; i < 4; i++) a[i] = Ps[ww*64 + ty*4 + i];
            const float4 b4 = *(const float4*)&Gs[ww*64 + tx*4];
            const float b[4] = {b4.x, b4.y, b4.z, b4.w};
            #pragma unroll
            for (int i = 0; i < 4; i++)
                #pragma unroll
                for (int j = 0; j < 4; j++)
                    m[i][j] = fmaf(a[i], b[j], m[i][j]);
        }
        __syncthreads();
    }
    #pragma unroll
    for (int i = 0; i < 4; i++)
        #pragma unroll
        for (int j = 0; j < 4; j++)
            if (tx*4 + j > ty*4 + i) m[i][j] = 0.f;
    #pragma unroll
    for (int i = 0; i < 4; i++)
        #pragma unroll
        for (int j = 0; j < 4; j++)
            sb[(ty*4+i)*65 + tx*4 + j] = m[i][j];
    __syncthreads();
    float mm[4][4] = {};
    #pragma unroll 8
    for (int jj = 0; jj < 64; jj++) {
        float a[4], b[4];
        #pragma unroll
        for (int i = 0; i < 4; i++) a[i] = sb[(ty*4+i)*65 + jj];
        #pragma unroll
        for (int j = 0; j < 4; j++) b[j] = sb[(tx*4+j)*65 + jj];
        #pragma unroll
        for (int i = 0; i < 4; i++)
            #pragma unroll
            for (int j = 0; j < 4; j++)
                mm[i][j] = fmaf(a[i], b[j], mm[i][j]);
    }
    #pragma unroll
    for (int i = 0; i < 4; i++)
        #pragma unroll
        for (int j = 0; j < 4; j++)
            g_M[(size_t)bn*K_*K_ + (ty*4+i)*K_ + tx*4 + j] = mm[i][j];
}

// ---------------------------------------------------------------------------
// Flash attention (R3 version, unchanged): 128q x 64k tiles, 8x4 micro.
// ---------------------------------------------------------------------------
#define KTP 65
__global__ __launch_bounds__(256)
void flash_kernel() {
    extern __shared__ __align__(16) float sm[];
    float* Qm_s = sm;
    float* Ps_s = sm + 8192;
    float* Kt_s = sm + 16384;

    const int tx = threadIdx.x, ty = threadIdx.y;
    const int t  = ty*16 + tx;
    const int bn = blockIdx.y;
    const int b  = bn >> 4, n = bn & 15;
    const int qt = 15 - (int)blockIdx.x;
    const int w0 = qt * 128;
    const float* Pp = g_P + (size_t)bn*W_*K_;
    const float* Mp = g_M + (size_t)bn*K_*K_;

    int R[8];
    #pragma unroll
    for (int i = 0; i < 8; i++) R[i] = (i < 4) ? ty*4 + i : 64 + ty*4 + (i-4);

    #pragma unroll
    for (int s = 0; s < 8; s++) {
        const int i4 = t + s*256;
        ((float4*)Ps_s)[i4] = ((const float4*)(Pp + (size_t)w0*K_))[i4];
    }
    #pragma unroll
    for (int s = 0; s < 16; s++) {
        const int idx = t + s*256;
        Kt_s[(idx >> 6)*KTP + (idx & 63)] = Mp[idx];
    }
    __syncthreads();
    {
        float q[8][4] = {};
        #pragma unroll 8
        for (int kk = 0; kk < 64; kk++) {
            float a[8], bb[4];
            #pragma unroll
            for (int i = 0; i < 8; i++) a[i] = Ps_s[R[i]*64 + kk];
            #pragma unroll
            for (int j = 0; j < 4; j++) bb[j] = Kt_s[kk*KTP + tx*4 + j];
            #pragma unroll
            for (int i = 0; i < 8; i++)
                #pragma unroll
                for (int j = 0; j < 4; j++)
                    q[i][j] = fmaf(a[i], bb[j], q[i][j]);
        }
        #pragma unroll
        for (int i = 0; i < 8; i++)
            *(float4*)&Qm_s[R[i]*64 + tx*4] =
                make_float4(q[i][0], q[i][1], q[i][2], q[i][3]);
    }

    float mrun[8], lrun[8], O[8][4] = {};
    #pragma unroll
    for (int i = 0; i < 8; i++) { mrun[i] = -INFINITY; lrun[i] = 0.f; }

    const int vmax = w0 + 64;
    for (int v0 = 0; v0 <= vmax; v0 += 64) {
        __syncthreads();
        {
            const int row = t >> 2;
            const int d0  = (t & 3) * 16;
            const float* src = Pp + (size_t)(v0 + row)*K_ + d0;
            #pragma unroll
            for (int qq = 0; qq < 4; qq++) {
                const float4 v = *(const float4*)(src + qq*4);
                Kt_s[(d0+qq*4+0)*KTP + row] = v.x;
                Kt_s[(d0+qq*4+1)*KTP + row] = v.y;
                Kt_s[(d0+qq*4+2)*KTP + row] = v.z;
                Kt_s[(d0+qq*4+3)*KTP + row] = v.w;
            }
        }
        __syncthreads();
        float s[8][4] = {};
        #pragma unroll 8
        for (int kk = 0; kk < 64; kk++) {
            float a[8], bb[4];
            #pragma unroll
            for (int i = 0; i < 8; i++) a[i] = Qm_s[R[i]*64 + kk];
            #pragma unroll
            for (int j = 0; j < 4; j++) bb[j] = Kt_s[kk*KTP + tx*4 + j];
            #pragma unroll
            for (int i = 0; i < 8; i++)
                #pragma unroll
                for (int j = 0; j < 4; j++)
                    s[i][j] = fmaf(a[i], bb[j], s[i][j]);
        }
        const bool needmask = (v0 >= w0);
        #pragma unroll
        for (int i = 0; i < 8; i++)
            #pragma unroll
            for (int j = 0; j < 4; j++) {
                s[i][j] *= 0.125f;
                if (needmask && (v0 + tx*4 + j > w0 + R[i])) s[i][j] = -INFINITY;
            }
        #pragma unroll
        for (int i = 0; i < 8; i++) {
            float rmax = fmaxf(fmaxf(s[i][0], s[i][1]), fmaxf(s[i][2], s[i][3]));
            #pragma unroll
            for (int off = 8; off >= 1; off >>= 1)
                rmax = fmaxf(rmax, __shfl_xor_sync(0xffffffffu, rmax, off));
            const float mn    = fmaxf(mrun[i], rmax);
            const float alpha = __expf(mrun[i] - mn);
            float4 pv;
            pv.x = __expf(s[i][0] - mn);
            pv.y = __expf(s[i][1] - mn);
            pv.z = __expf(s[i][2] - mn);
            pv.w = __expf(s[i][3] - mn);
            *(float4*)&Ps_s[R[i]*64 + tx*4] = pv;
            float rsum = pv.x + pv.y + pv.z + pv.w;
            #pragma unroll
            for (int off = 8; off >= 1; off >>= 1)
                rsum += __shfl_xor_sync(0xffffffffu, rsum, off);
            lrun[i] = lrun[i]*alpha + rsum;
            mrun[i] = mn;
            #pragma unroll
            for (int j = 0; j < 4; j++) O[i][j] *= alpha;
        }
        __syncthreads();
        #pragma unroll 8
        for (int c = 0; c < 64; c++) {
            float a[8], bb[4];
            #pragma unroll
            for (int i = 0; i < 8; i++) a[i] = Ps_s[R[i]*64 + c];
            #pragma unroll
            for (int j = 0; j < 4; j++) bb[j] = Kt_s[(tx*4+j)*KTP + c];
            #pragma unroll
            for (int i = 0; i < 8; i++)
                #pragma unroll
                for (int j = 0; j < 4; j++)
                    O[i][j] = fmaf(a[i], bb[j], O[i][j]);
        }
    }
    #pragma unroll
    for (int i = 0; i < 8; i++) {
        const float inv = 1.0f / lrun[i];
        const int w = w0 + R[i];
        *(float4*)&g_Ng[((size_t)(b*W_ + w))*C_ + n*K_ + tx*4] =
            make_float4(O[i][0]*inv, O[i][1]*inv, O[i][2]*inv, O[i][3]*inv);
    }
}

// ---------------------------------------------------------------------------
extern "C" void kernel_launch(void* const* d_in, const int* in_sizes, int n_in,
                              void* d_out, int out_size) {
    const float* x  = (const float*)d_in[0];
    const float* Wp = (const float*)d_in[1];
    const float* bp = (const float*)d_in[2];
    const float* G  = (const float*)d_in[3];
    const float* Wm = (const float*)d_in[4];
    const float* bm = (const float*)d_in[5];
    float* out = (float*)d_out;

    cudaFuncSetAttribute(flash_kernel, cudaFuncAttributeMaxDynamicSharedMemorySize,
                         (8192 + 8192 + 64*KTP) * (int)sizeof(float));
    cudaFuncSetAttribute(mma_gemm<0>, cudaFuncAttributeMaxDynamicSharedMemorySize, MG_SMEM);
    cudaFuncSetAttribute(mma_gemm<1>, cudaFuncAttributeMaxDynamicSharedMemorySize, MG_SMEM);

    void *pAhi, *pAlo, *pBhi, *pBlo, *pNg;
    cudaGetSymbolAddress(&pAhi, g_Ahi);
    cudaGetSymbolAddress(&pAlo, g_Alo);
    cudaGetSymbolAddress(&pBhi, g_Bhi);
    cudaGetSymbolAddress(&pBlo, g_Blo);
    cudaGetSymbolAddress(&pNg,  g_Ng);

    const int nA4 = (B_*W_*C_) / 4;
    const int nW4 = (C_*C_) / 4;
    dim3 blk(16, 16);

    convert_kernel<<<nA4/256, 256>>>(x,  (__nv_bfloat16*)pAhi, (__nv_bfloat16*)pAlo, nA4);
    convert_kernel<<<nW4/256, 256>>>(Wp, (__nv_bfloat16*)pBhi, (__nv_bfloat16*)pBlo, nW4);
    mma_gemm<0><<<dim3(8, 32), 256, MG_SMEM>>>(bp, nullptr);
    mbuild_kernel<<<32, blk>>>(G);
    flash_kernel<<<dim3(16, 32), blk, (8192 + 8192 + 64*KTP)*sizeof(float)>>>();
    convert_kernel<<<nA4/256, 256>>>((const float*)pNg, (__nv_bfloat16*)pAhi, (__nv_bfloat16*)pAlo, nA4);
    convert_kernel<<<nW4/256, 256>>>(Wm, (__nv_bfloat16*)pBhi, (__nv_bfloat16*)pBlo, nW4);
    mma_gemm<1><<<dim3(8, 32), 256, MG_SMEM>>>(bm, out);
}

// round 6
// speedup vs baseline: 2.4153x; 1.5226x over previous
#include <cuda_runtime.h>
#include <cuda_bf16.h>
#include <math.h>
#include <cstdint>

#define B_ 2
#define W_ 2048
#define C_ 1024
#define N_ 16
#define K_ 64
#define HEADS (B_*N_)

__device__ float g_P [B_*N_*W_*K_];     // P in [b][n][w][k] layout
__device__ float g_M [HEADS*K_*K_];     // mm per head
__device__ float g_Mp[HEADS*8*K_*K_];   // mbuild partials
__device__ float g_Ng[B_*W_*C_];        // nudged in [b][w][c] layout

__device__ __nv_bfloat16 g_Ahi[(size_t)B_*W_*C_];
__device__ __nv_bfloat16 g_Alo[(size_t)B_*W_*C_];
__device__ __nv_bfloat16 g_Bhi[(size_t)C_*C_];
__device__ __nv_bfloat16 g_Blo[(size_t)C_*C_];

// ---------------- helpers (plain sm_80-class PTX only) ----------------
__device__ __forceinline__ uint32_t smem_u32(const void* p) {
    uint32_t a;
    asm("{ .reg .u64 t; cvta.to.shared.u64 t, %1; cvt.u32.u64 %0, t; }" : "=r"(a) : "l"(p));
    return a;
}
__device__ __forceinline__ void ldsm_x4(uint32_t* r, uint32_t addr) {
    asm volatile("ldmatrix.sync.aligned.m8n8.x4.shared.b16 {%0,%1,%2,%3}, [%4];"
        : "=r"(r[0]), "=r"(r[1]), "=r"(r[2]), "=r"(r[3]) : "r"(addr));
}
__device__ __forceinline__ void ldsm_x2(uint32_t* r, uint32_t addr) {
    asm volatile("ldmatrix.sync.aligned.m8n8.x2.shared.b16 {%0,%1}, [%2];"
        : "=r"(r[0]), "=r"(r[1]) : "r"(addr));
}
__device__ __forceinline__ void mma_bf16(float* d, const uint32_t* a, const uint32_t* b) {
    asm volatile("mma.sync.aligned.m16n8k16.row.col.f32.bf16.bf16.f32 "
        "{%0,%1,%2,%3}, {%4,%5,%6,%7}, {%8,%9}, {%0,%1,%2,%3};"
        : "+f"(d[0]), "+f"(d[1]), "+f"(d[2]), "+f"(d[3])
        : "r"(a[0]), "r"(a[1]), "r"(a[2]), "r"(a[3]), "r"(b[0]), "r"(b[1]));
}
__device__ __forceinline__ void mma_tf32(float* d, const uint32_t* a, const uint32_t* b) {
    asm volatile("mma.sync.aligned.m16n8k8.row.col.f32.tf32.tf32.f32 "
        "{%0,%1,%2,%3}, {%4,%5,%6,%7}, {%8,%9}, {%0,%1,%2,%3};"
        : "+f"(d[0]), "+f"(d[1]), "+f"(d[2]), "+f"(d[3])
        : "r"(a[0]), "r"(a[1]), "r"(a[2]), "r"(a[3]), "r"(b[0]), "r"(b[1]));
}
__device__ __forceinline__ uint32_t f2tf32(float f) {
    uint32_t u; asm("cvt.rna.tf32.f32 %0, %1;" : "=r"(u) : "f"(f)); return u;
}
__device__ __forceinline__ void split_bf16x2(float x, float y, uint32_t& h, uint32_t& l) {
    __nv_bfloat16 hx = __float2bfloat16(x), hy = __float2bfloat16(y);
    __nv_bfloat16 lx = __float2bfloat16(x - __bfloat162float(hx));
    __nv_bfloat16 ly = __float2bfloat16(y - __bfloat162float(hy));
    __nv_bfloat162 hh = __halves2bfloat162(hx, hy);
    __nv_bfloat162 ll = __halves2bfloat162(lx, ly);
    h = *(uint32_t*)&hh; l = *(uint32_t*)&ll;
}

// ---------------------------------------------------------------------------
// fp32 -> (bf16 hi, bf16 lo)
// ---------------------------------------------------------------------------
__global__ __launch_bounds__(256)
void convert_kernel(const float* __restrict__ src, __nv_bfloat16* __restrict__ hi,
                    __nv_bfloat16* __restrict__ lo, int n4) {
    const int i = blockIdx.x * blockDim.x + threadIdx.x;
    if (i >= n4) return;
    const float4 v = ((const float4*)src)[i];
    uint32_t h0, l0, h1, l1;
    split_bf16x2(v.x, v.y, h0, l0);
    split_bf16x2(v.z, v.w, h1, l1);
    ((uint32_t*)hi)[i*2+0] = h0; ((uint32_t*)hi)[i*2+1] = h1;
    ((uint32_t*)lo)[i*2+0] = l0; ((uint32_t*)lo)[i*2+1] = l1;
}

// ---------------------------------------------------------------------------
// HMMA bf16x3 GEMM (unchanged from R5)
// ---------------------------------------------------------------------------
#define PITCH 72
#define MG_SMEM (4 * 128 * PITCH * 2)

template<int MODE>
__global__ __launch_bounds__(256)
void mma_gemm(const float* __restrict__ bias, float* __restrict__ out) {
    extern __shared__ __align__(16) __nv_bfloat16 sb[];
    __nv_bfloat16* Ash = sb;
    __nv_bfloat16* Asl = sb + 128*PITCH;
    __nv_bfloat16* Bsh = sb + 2*128*PITCH;
    __nv_bfloat16* Bsl = sb + 3*128*PITCH;
    const int tid = threadIdx.x, lane = tid & 31, wid = tid >> 5;
    const int wm = wid >> 2, wn = wid & 3;
    const int r0 = blockIdx.y*128, c0 = blockIdx.x*128;

    float acc[4][4][4] = {};

    for (int k0 = 0; k0 < C_; k0 += 64) {
        #pragma unroll
        for (int s = 0; s < 4; s++) {
            const int idx = tid + s*256;
            const int row = idx >> 3, q = idx & 7;
            const size_t ga = (size_t)(r0 + row)*C_ + k0 + q*8;
            const size_t gb = (size_t)(c0 + row)*C_ + k0 + q*8;
            *(uint4*)&Ash[row*PITCH + q*8] = *(const uint4*)(g_Ahi + ga);
            *(uint4*)&Asl[row*PITCH + q*8] = *(const uint4*)(g_Alo + ga);
            *(uint4*)&Bsh[row*PITCH + q*8] = *(const uint4*)(g_Bhi + gb);
            *(uint4*)&Bsl[row*PITCH + q*8] = *(const uint4*)(g_Blo + gb);
        }
        __syncthreads();
        #pragma unroll
        for (int ks = 0; ks < 4; ks++) {
            const int kk = ks * 16;
            uint32_t bh[4][2], bl[4][2];
            {
                const int row = wn*32 + (lane & 7);
                const int col = kk + ((lane >> 3) & 1) * 8;
                #pragma unroll
                for (int ni = 0; ni < 4; ni++) {
                    ldsm_x2(bh[ni], smem_u32(&Bsh[(row + ni*8)*PITCH + col]));
                    ldsm_x2(bl[ni], smem_u32(&Bsl[(row + ni*8)*PITCH + col]));
                }
            }
            #pragma unroll
            for (int mi = 0; mi < 4; mi++) {
                uint32_t ah[4], al[4];
                const int row = wm*64 + mi*16 + (lane & 15);
                const int col = kk + (lane >> 4) * 8;
                ldsm_x4(ah, smem_u32(&Ash[row*PITCH + col]));
                ldsm_x4(al, smem_u32(&Asl[row*PITCH + col]));
                #pragma unroll
                for (int ni = 0; ni < 4; ni++) {
                    mma_bf16(acc[mi][ni], ah, bh[ni]);
                    mma_bf16(acc[mi][ni], ah, bl[ni]);
                    mma_bf16(acc[mi][ni], al, bh[ni]);
                }
            }
        }
        __syncthreads();
    }

    #pragma unroll
    for (int mi = 0; mi < 4; mi++) {
        #pragma unroll
        for (int ni = 0; ni < 4; ni++) {
            #pragma unroll
            for (int h = 0; h < 2; h++) {
                const int r = r0 + wm*64 + mi*16 + (lane >> 2) + h*8;
                const int c = c0 + wn*32 + ni*8 + (lane & 3)*2;
                float2 v;
                v.x = acc[mi][ni][h*2+0] + __ldg(bias + c);
                v.y = acc[mi][ni][h*2+1] + __ldg(bias + c + 1);
                if (MODE == 0) {
                    const int bb = r >> 11, w = r & (W_-1);
                    const int n  = c >> 6,  kb = c & (K_-1);
                    *(float2*)&g_P[(((size_t)(bb*N_+n))*W_ + w)*K_ + kb] = v;
                } else {
                    *(float2*)&out[(size_t)r*C_ + c] = v;
                }
            }
        }
    }
}

// ---------------------------------------------------------------------------
// mbuild phase A: partial m over a 256-w chunk (grid 8 x 32)
// ---------------------------------------------------------------------------
__global__ __launch_bounds__(256)
void mbuildA(const float* __restrict__ G) {
    __shared__ __align__(16) float sb[64*64];
    float* Ps = sb;
    float* Gs = sb + 2048;
    const int tx = threadIdx.x, ty = threadIdx.y;
    const int t  = ty*16 + tx;
    const int bn = blockIdx.y, ch = blockIdx.x;
    const int n  = bn & (N_-1);
    const float* Pp = g_P + (size_t)bn*W_*K_;
    const float* Gp = G   + (size_t)n *W_*K_;

    float m[4][4] = {};
    for (int w0 = ch*256; w0 < ch*256 + 256; w0 += 32) {
        #pragma unroll
        for (int s = 0; s < 2; s++) {
            const int i4 = t + s*256;
            ((float4*)Ps)[i4] = ((const float4*)(Pp + (size_t)w0*K_))[i4];
            ((float4*)Gs)[i4] = ((const float4*)(Gp + (size_t)w0*K_))[i4];
        }
        __syncthreads();
        #pragma unroll 8
        for (int ww = 0; ww < 32; ww++) {
            float a[4];
            #pragma unroll
            for (int i = 0; i < 4; i++) a[i] = Ps[ww*64 + ty*4 + i];
            const float4 b4 = *(const float4*)&Gs[ww*64 + tx*4];
            const float b[4] = {b4.x, b4.y, b4.z, b4.w};
            #pragma unroll
            for (int i = 0; i < 4; i++)
                #pragma unroll
                for (int j = 0; j < 4; j++)
                    m[i][j] = fmaf(a[i], b[j], m[i][j]);
        }
        __syncthreads();
    }
    float* dst = g_Mp + ((size_t)bn*8 + ch)*4096;
    #pragma unroll
    for (int i = 0; i < 4; i++)
        #pragma unroll
        for (int j = 0; j < 4; j++)
            dst[(ty*4+i)*64 + tx*4 + j] = m[i][j];
}

// ---------------------------------------------------------------------------
// mbuild phase B: reduce partials, mask, mm = m m^T   (grid 32)
// ---------------------------------------------------------------------------
__global__ __launch_bounds__(256)
void mbuildB() {
    __shared__ float sb[64*65];
    const int tx = threadIdx.x, ty = threadIdx.y;
    const int bn = blockIdx.x;
    float m[4][4] = {};
    const float* src = g_Mp + (size_t)bn*8*4096;
    #pragma unroll
    for (int ch = 0; ch < 8; ch++)
        #pragma unroll
        for (int i = 0; i < 4; i++)
            #pragma unroll
            for (int j = 0; j < 4; j++)
                m[i][j] += src[ch*4096 + (ty*4+i)*64 + tx*4 + j];
    #pragma unroll
    for (int i = 0; i < 4; i++)
        #pragma unroll
        for (int j = 0; j < 4; j++)
            if (tx*4 + j > ty*4 + i) m[i][j] = 0.f;
    #pragma unroll
    for (int i = 0; i < 4; i++)
        #pragma unroll
        for (int j = 0; j < 4; j++)
            sb[(ty*4+i)*65 + tx*4 + j] = m[i][j];
    __syncthreads();
    float mm[4][4] = {};
    #pragma unroll 8
    for (int jj = 0; jj < 64; jj++) {
        float a[4], b[4];
        #pragma unroll
        for (int i = 0; i < 4; i++) a[i] = sb[(ty*4+i)*65 + jj];
        #pragma unroll
        for (int j = 0; j < 4; j++) b[j] = sb[(tx*4+j)*65 + jj];
        #pragma unroll
        for (int i = 0; i < 4; i++)
            #pragma unroll
            for (int j = 0; j < 4; j++)
                mm[i][j] = fmaf(a[i], b[j], mm[i][j]);
    }
    #pragma unroll
    for (int i = 0; i < 4; i++)
        #pragma unroll
        for (int j = 0; j < 4; j++)
            g_M[(size_t)bn*K_*K_ + (ty*4+i)*K_ + tx*4 + j] = mm[i][j];
}

// ---------------------------------------------------------------------------
// Flash attention, tensor-core edition.
// 128q x 64k tiles, 8 warps (warp w owns q rows 16w..16w+15).
// GEMM1 (S = Qm K^T): 3xTF32 m16n8k8.  GEMM2 (O += P~ V): bf16x3 m16n8k16,
// A packed from S accumulators in registers (scores never touch smem).
// smem: Qh/Ql fp32[128][68], Kh/Kl fp32[64][72] ([dim][key]),
//       Vh/Vl bf16[64][72] ([dim][key]).  Total 124928 B.
// ---------------------------------------------------------------------------
#define QP 68
#define KP 72
#define FL_SMEM 124928

__global__ __launch_bounds__(256)
void flash_kernel() {
    extern __shared__ __align__(16) float fsm[];
    float* Qh = fsm;                 // 128*68 = 8704
    float* Ql = fsm + 8704;          // 8704
    float* Kh = fsm + 17408;         // 64*72 = 4608
    float* Kl = fsm + 22016;         // 4608
    __nv_bfloat16* Vh = (__nv_bfloat16*)(fsm + 26624);   // 64*72 bf16
    __nv_bfloat16* Vl = (__nv_bfloat16*)(fsm + 28928);

    const int t = threadIdx.x;
    const int lane = t & 31, wid = t >> 5;
    const int bn = blockIdx.y;
    const int b = bn >> 4, n = bn & 15;
    const int qt = 15 - (int)blockIdx.x;   // heavy first
    const int w0 = qt * 128;
    const float* Pp = g_P + (size_t)bn*W_*K_;
    const float* Mp = g_M + (size_t)bn*K_*K_;

    // ---- Prologue: Pq -> Qh (flat pitch 64), M -> Kh (pitch KP) ----
    #pragma unroll
    for (int s = 0; s < 8; s++) {
        const int i4 = t + s*256;
        ((float4*)Qh)[i4] = ((const float4*)(Pp + (size_t)w0*K_))[i4];
    }
    #pragma unroll
    for (int s = 0; s < 16; s++) {
        const int idx = t + s*256;
        Kh[(idx >> 6)*KP + (idx & 63)] = Mp[idx];
    }
    __syncthreads();
    {
        const int trow = t >> 4, tcol = t & 15;
        int R[8];
        #pragma unroll
        for (int i = 0; i < 8; i++) R[i] = (i < 4) ? trow*4 + i : 64 + trow*4 + (i-4);
        float q[8][4] = {};
        #pragma unroll 4
        for (int kk = 0; kk < 64; kk++) {
            float a[8], bb[4];
            #pragma unroll
            for (int i = 0; i < 8; i++) a[i] = Qh[R[i]*64 + kk];
            #pragma unroll
            for (int j = 0; j < 4; j++) bb[j] = Kh[kk*KP + tcol*4 + j];
            #pragma unroll
            for (int i = 0; i < 8; i++)
                #pragma unroll
                for (int j = 0; j < 4; j++)
                    q[i][j] = fmaf(a[i], bb[j], q[i][j]);
        }
        __syncthreads();
        #pragma unroll
        for (int i = 0; i < 8; i++)
            #pragma unroll
            for (int j = 0; j < 4; j++) {
                const float v = q[i][j];
                const float fh = __uint_as_float(f2tf32(v));
                Qh[R[i]*QP + tcol*4 + j] = fh;
                Ql[R[i]*QP + tcol*4 + j] = __uint_as_float(f2tf32(v - fh));
            }
    }

    const int qrow = wid * 16;
    const int q0 = w0 + qrow + (lane >> 2);
    const int q1 = q0 + 8;
    float mrun0 = -INFINITY, mrun1 = -INFINITY, lrun0 = 0.f, lrun1 = 0.f;
    float oacc[8][4] = {};

    for (int v0 = 0; v0 <= w0 + 64; v0 += 64) {
        __syncthreads();   // Qm ready (iter0) / K,V smem free (later)
        // ---- K tile: transpose + split (tf32 for GEMM1 B, bf16 for GEMM2 B)
        {
            const int row = t >> 2;            // key 0..63
            const int d0  = (t & 3) * 16;
            const float* src = Pp + (size_t)(v0 + row)*K_ + d0;
            #pragma unroll
            for (int qq = 0; qq < 4; qq++) {
                const float4 v = *(const float4*)(src + qq*4);
                const float vv[4] = {v.x, v.y, v.z, v.w};
                #pragma unroll
                for (int c = 0; c < 4; c++) {
                    const int d = d0 + qq*4 + c;
                    const float kv = vv[c];
                    const float fh = __uint_as_float(f2tf32(kv));
                    Kh[d*KP + row] = fh;
                    Kl[d*KP + row] = __uint_as_float(f2tf32(kv - fh));
                    const __nv_bfloat16 bh = __float2bfloat16(kv);
                    Vh[d*KP + row] = bh;
                    Vl[d*KP + row] = __float2bfloat16(kv - __bfloat162float(bh));
                }
            }
        }
        __syncthreads();

        if (v0 <= w0 + qrow + 15) {            // warp has live rows in this tile
            // ---- GEMM1: S = Qm @ K^T (3xTF32) ----
            float sacc[8][4] = {};
            #pragma unroll
            for (int ks = 0; ks < 8; ks++) {
                uint32_t ah[4], al[4];
                const int ar0 = qrow + (lane >> 2), ar1 = ar0 + 8;
                const int ac  = ks*8 + (lane & 3);
                ah[0] = *(uint32_t*)&Qh[ar0*QP + ac];
                ah[1] = *(uint32_t*)&Qh[ar1*QP + ac];
                ah[2] = *(uint32_t*)&Qh[ar0*QP + ac + 4];
                ah[3] = *(uint32_t*)&Qh[ar1*QP + ac + 4];
                al[0] = *(uint32_t*)&Ql[ar0*QP + ac];
                al[1] = *(uint32_t*)&Ql[ar1*QP + ac];
                al[2] = *(uint32_t*)&Ql[ar0*QP + ac + 4];
                al[3] = *(uint32_t*)&Ql[ar1*QP + ac + 4];
                #pragma unroll
                for (int nt = 0; nt < 8; nt++) {
                    uint32_t bh[2], bl[2];
                    const int bc = nt*8 + (lane >> 2);
                    const int br = ks*8 + (lane & 3);
                    bh[0] = *(uint32_t*)&Kh[br*KP + bc];
                    bh[1] = *(uint32_t*)&Kh[(br+4)*KP + bc];
                    bl[0] = *(uint32_t*)&Kl[br*KP + bc];
                    bl[1] = *(uint32_t*)&Kl[(br+4)*KP + bc];
                    mma_tf32(sacc[nt], ah, bl);
                    mma_tf32(sacc[nt], al, bh);
                    mma_tf32(sacc[nt], ah, bh);
                }
            }
            // ---- softmax (registers only) ----
            const bool dm = (v0 + 63 > w0 + qrow);
            float mx0 = -INFINITY, mx1 = -INFINITY;
            #pragma unroll
            for (int nt = 0; nt < 8; nt++)
                #pragma unroll
                for (int j = 0; j < 2; j++) {
                    const int key = v0 + nt*8 + (lane & 3)*2 + j;
                    float s0 = sacc[nt][j]   * 0.125f;
                    float s1 = sacc[nt][2+j] * 0.125f;
                    if (dm && key > q0) s0 = -INFINITY;
                    if (dm && key > q1) s1 = -INFINITY;
                    sacc[nt][j] = s0; sacc[nt][2+j] = s1;
                    mx0 = fmaxf(mx0, s0); mx1 = fmaxf(mx1, s1);
                }
            mx0 = fmaxf(mx0, __shfl_xor_sync(0xffffffffu, mx0, 1));
            mx0 = fmaxf(mx0, __shfl_xor_sync(0xffffffffu, mx0, 2));
            mx1 = fmaxf(mx1, __shfl_xor_sync(0xffffffffu, mx1, 1));
            mx1 = fmaxf(mx1, __shfl_xor_sync(0xffffffffu, mx1, 2));
            const float mn0 = fmaxf(mrun0, mx0), mn1 = fmaxf(mrun1, mx1);
            const float al0 = __expf(mrun0 - mn0), al1 = __expf(mrun1 - mn1);
            float sum0 = 0.f, sum1 = 0.f;
            #pragma unroll
            for (int nt = 0; nt < 8; nt++)
                #pragma unroll
                for (int j = 0; j < 2; j++) {
                    const float p0 = __expf(sacc[nt][j]   - mn0);
                    const float p1 = __expf(sacc[nt][2+j] - mn1);
                    sacc[nt][j] = p0; sacc[nt][2+j] = p1;
                    sum0 += p0; sum1 += p1;
                }
            sum0 += __shfl_xor_sync(0xffffffffu, sum0, 1);
            sum0 += __shfl_xor_sync(0xffffffffu, sum0, 2);
            sum1 += __shfl_xor_sync(0xffffffffu, sum1, 1);
            sum1 += __shfl_xor_sync(0xffffffffu, sum1, 2);
            lrun0 = lrun0*al0 + sum0; lrun1 = lrun1*al1 + sum1;
            mrun0 = mn0; mrun1 = mn1;
            #pragma unroll
            for (int dt = 0; dt < 8; dt++) {
                oacc[dt][0] *= al0; oacc[dt][1] *= al0;
                oacc[dt][2] *= al1; oacc[dt][3] *= al1;
            }
            // ---- GEMM2: O += P~ @ V (bf16x3, A from registers) ----
            #pragma unroll
            for (int s4 = 0; s4 < 4; s4++) {
                uint32_t ah[4], al[4];
                split_bf16x2(sacc[2*s4][0],   sacc[2*s4][1],   ah[0], al[0]);
                split_bf16x2(sacc[2*s4][2],   sacc[2*s4][3],   ah[1], al[1]);
                split_bf16x2(sacc[2*s4+1][0], sacc[2*s4+1][1], ah[2], al[2]);
                split_bf16x2(sacc[2*s4+1][2], sacc[2*s4+1][3], ah[3], al[3]);
                const int col = s4*16 + ((lane >> 3) & 1) * 8;
                #pragma unroll
                for (int dt = 0; dt < 8; dt++) {
                    uint32_t bh[2], bl[2];
                    const int row = dt*8 + (lane & 7);
                    ldsm_x2(bh, smem_u32(&Vh[row*KP + col]));
                    ldsm_x2(bl, smem_u32(&Vl[row*KP + col]));
                    mma_bf16(oacc[dt], ah, bh);
                    mma_bf16(oacc[dt], ah, bl);
                    mma_bf16(oacc[dt], al, bh);
                }
            }
        }
    }
    // ---- Epilogue ----
    const float inv0 = 1.0f / lrun0, inv1 = 1.0f / lrun1;
    #pragma unroll
    for (int dt = 0; dt < 8; dt++) {
        const int c = n*K_ + dt*8 + (lane & 3)*2;
        *(float2*)&g_Ng[((size_t)(b*W_ + q0))*C_ + c] =
            make_float2(oacc[dt][0]*inv0, oacc[dt][1]*inv0);
        *(float2*)&g_Ng[((size_t)(b*W_ + q1))*C_ + c] =
            make_float2(oacc[dt][2]*inv1, oacc[dt][3]*inv1);
    }
}

// ---------------------------------------------------------------------------
extern "C" void kernel_launch(void* const* d_in, const int* in_sizes, int n_in,
                              void* d_out, int out_size) {
    const float* x  = (const float*)d_in[0];
    const float* Wp = (const float*)d_in[1];
    const float* bp = (const float*)d_in[2];
    const float* G  = (const float*)d_in[3];
    const float* Wm = (const float*)d_in[4];
    const float* bm = (const float*)d_in[5];
    float* out = (float*)d_out;

    cudaFuncSetAttribute(flash_kernel, cudaFuncAttributeMaxDynamicSharedMemorySize, FL_SMEM);
    cudaFuncSetAttribute(mma_gemm<0>, cudaFuncAttributeMaxDynamicSharedMemorySize, MG_SMEM);
    cudaFuncSetAttribute(mma_gemm<1>, cudaFuncAttributeMaxDynamicSharedMemorySize, MG_SMEM);

    void *pAhi, *pAlo, *pBhi, *pBlo, *pNg;
    cudaGetSymbolAddress(&pAhi, g_Ahi);
    cudaGetSymbolAddress(&pAlo, g_Alo);
    cudaGetSymbolAddress(&pBhi, g_Bhi);
    cudaGetSymbolAddress(&pBlo, g_Blo);
    cudaGetSymbolAddress(&pNg,  g_Ng);

    const int nA4 = (B_*W_*C_) / 4;
    const int nW4 = (C_*C_) / 4;
    dim3 blk(16, 16);

    convert_kernel<<<nA4/256, 256>>>(x,  (__nv_bfloat16*)pAhi, (__nv_bfloat16*)pAlo, nA4);
    convert_kernel<<<nW4/256, 256>>>(Wp, (__nv_bfloat16*)pBhi, (__nv_bfloat16*)pBlo, nW4);
    mma_gemm<0><<<dim3(8, 32), 256, MG_SMEM>>>(bp, nullptr);
    mbuildA<<<dim3(8, 32), blk>>>(G);
    mbuildB<<<32, blk>>>();
    flash_kernel<<<dim3(16, 32), 256, FL_SMEM>>>();
    convert_kernel<<<nA4/256, 256>>>((const float*)pNg, (__nv_bfloat16*)pAhi, (__nv_bfloat16*)pAlo, nA4);
    convert_kernel<<<nW4/256, 256>>>(Wm, (__nv_bfloat16*)pBhi, (__nv_bfloat16*)pBlo, nW4);
    mma_gemm<1><<<dim3(8, 32), 256, MG_SMEM>>>(bm, out);
}